// round 12
// baseline (speedup 1.0000x reference)
#include <cuda_runtime.h>
#include <cstdint>

// ============================================================================
// Inverse NTT over F_P, P = 2013265921, N = 2^22, C = 4. Four-step 2048x2048.
// R12 = R11 with SHOUP multiplication replacing Montgomery everywhere:
//   w' = floor(w*2^32/P) precomputed per twiddle; w*x mod P = 3 IMAD + 1 min.
//   Valid for x < 2P (lazy-subtract feeds it directly). Data in plain domain.
// Tables: T1[k]=(w,w') for w=omega^-{2048k}; T2[j]=(w,w') for w=omega^-j*ninv.
// ============================================================================

static constexpr uint32_t MOD    = 2013265921u;
static constexpr uint32_t N_FULL = 1u << 22;
static constexpr uint32_t N_HALF = 1u << 21;

#define DT_I32 0
#define DT_I64 1
#define DT_F32 2
#define DT_F64 3

static constexpr int COLPAD = 2305;       // padded uint4 stride per column
static constexpr int SMEM_A_BYTES = 2 * COLPAD * 16 + 2048 * 8 * 2;  // 106528
static constexpr int SMEM_B_BYTES = 2 * COLPAD * 16 + 1024 * 8;      //  81952

__device__ uint2 g_T1[2048];              // (w, w') for omega^-{2048k}
__device__ uint2 g_T2[2048];              // (w, w') for omega^-j * n_inv
__device__ uint4 g_buf[N_FULL];           // 64 MB intermediate
__device__ int   g_dtype;

// Named barrier: 256 threads of group (id-1). Per-CTA resource.
#define NB(id) asm volatile("bar.sync %0, 256;" :: "r"(id) : "memory")

// ---------------- modular primitives (branch-free) ----------------
// Shoup: q = mulhi(w', x); r = w*x - q*P (mod 2^32) in [0,2P); min -> [0,P).
// Requires x < 2^32 (we feed x < 2P) and w < P.
__device__ __forceinline__ uint32_t shmul(uint2 w, uint32_t x) {
    uint32_t q = __umulhi(w.y, x);
    uint32_t r = w.x * x - q * MOD;
    return min(r, r - MOD);
}
__device__ __forceinline__ uint32_t addm(uint32_t a, uint32_t b) {
    uint32_t s = a + b; return min(s, s - MOD);
}
__device__ __forceinline__ uint32_t subm(uint32_t a, uint32_t b) {
    uint32_t d = a - b; return min(d, d + MOD);
}
__device__ __forceinline__ uint32_t subl(uint32_t a, uint32_t b) {
    return a - b + MOD;                   // lazy: < 2P, only feeds shmul
}

__device__ __forceinline__ void bfly(uint4& lo, uint4& hi, uint2 tw) {
    uint32_t a, d;
    a = addm(lo.x, hi.x); d = subl(lo.x, hi.x); lo.x = a; hi.x = shmul(tw, d);
    a = addm(lo.y, hi.y); d = subl(lo.y, hi.y); lo.y = a; hi.y = shmul(tw, d);
    a = addm(lo.z, hi.z); d = subl(lo.z, hi.z); lo.z = a; hi.z = shmul(tw, d);
    a = addm(lo.w, hi.w); d = subl(lo.w, hi.w); lo.w = a; hi.w = shmul(tw, d);
}
__device__ __forceinline__ void bfly1(uint4& lo, uint4& hi) {   // twiddle == 1
    uint32_t a, d;
    a = addm(lo.x, hi.x); d = subm(lo.x, hi.x); lo.x = a; hi.x = d;
    a = addm(lo.y, hi.y); d = subm(lo.y, hi.y); lo.y = a; hi.y = d;
    a = addm(lo.z, hi.z); d = subm(lo.z, hi.z); lo.z = a; hi.z = d;
    a = addm(lo.w, hi.w); d = subm(lo.w, hi.w); lo.w = a; hi.w = d;
}

// Three consecutive DIF stages (halves 4S, 2S, S); twiddle exponent for
// half H at lo-position p is (p mod H) * (1024/H). tw = smem T1 low half.
template <int S>
__device__ __forceinline__ void dif_group(uint4 x[8], int base,
                                          const uint2* tw) {
#pragma unroll
    for (int j = 0; j < 4; ++j) {                       // half = 4S
        int p = base + j * S;
        bfly(x[j], x[j + 4], tw[(p & (4 * S - 1)) * (256 / S)]);
    }
#pragma unroll
    for (int k = 0; k < 4; ++k) {                       // half = 2S
        int j = (k & 1) + ((k & 2) << 1);
        int p = base + j * S;
        bfly(x[j], x[j + 2], tw[(p & (2 * S - 1)) * (512 / S)]);
    }
#pragma unroll
    for (int j = 0; j < 8; j += 2) {                    // half = S
        int p = base + j * S;
        bfly(x[j], x[j + 1], tw[(p & (S - 1)) * (1024 / S)]);
    }
}

__device__ __forceinline__ int padi(int i) { return i + (i >> 3); }

// In-place size-2048 DIF (validated choreography). Entry: x[j] = point
// (t+256j). Exit: x[j] = storage slot (8t+j); slot r holds output brev11(r).
__device__ __forceinline__ void dif2048(uint4 x[8], int t, uint4* sm,
                                        const uint2* tw, int bid) {
    dif_group<256>(x, t, tw);                           // halves 1024,512,256
#pragma unroll
    for (int j = 0; j < 8; ++j) sm[padi(t + 256 * j)] = x[j];
    NB(bid);
    int b1 = ((t >> 5) << 8) | (t & 31);
#pragma unroll
    for (int j = 0; j < 8; ++j) x[j] = sm[padi(b1 + 32 * j)];
    dif_group<32>(x, b1, tw);                           // halves 128,64,32
    NB(bid);
#pragma unroll
    for (int j = 0; j < 8; ++j) sm[padi(b1 + 32 * j)] = x[j];
    NB(bid);
    int b2 = ((t >> 2) << 5) | (t & 3);
#pragma unroll
    for (int j = 0; j < 8; ++j) x[j] = sm[padi(b2 + 4 * j)];
    dif_group<4>(x, b2, tw);                            // halves 16,8,4
    NB(bid);
#pragma unroll
    for (int j = 0; j < 8; ++j) sm[padi(b2 + 4 * j)] = x[j];
    NB(bid);
#pragma unroll
    for (int j = 0; j < 8; ++j) x[j] = sm[padi(8 * t + j)];
    uint2 w512 = tw[512];                               // halves 2,1
    bfly1(x[0], x[2]); bfly(x[1], x[3], w512);
    bfly1(x[4], x[6]); bfly(x[5], x[7], w512);
    bfly1(x[0], x[1]); bfly1(x[2], x[3]);
    bfly1(x[4], x[5]); bfly1(x[6], x[7]);
}

// dtype probe (tw[0] == 1 in every encoding):
//   int64: w0=1,w1=0   int32: w0=1,w1!=0   f64: w0=0   f32: w0=0x3F800000
__device__ __forceinline__ int probe_dtype(const void* tw) {
    const uint32_t* w = (const uint32_t*)tw;
    if (w[0] == 1u) return (w[1] == 0u) ? DT_I64 : DT_I32;
    if (w[0] == 0u) return DT_F64;
    return DT_F32;
}
__device__ __forceinline__ uint32_t load_elem(const void* p, size_t i, int dt) {
    switch (dt) {
        case DT_I64: return (uint32_t)((const unsigned long long*)p)[i];
        case DT_F64: return (uint32_t)__double2ll_rn(((const double*)p)[i]);
        case DT_F32: return (uint32_t)__float2ll_rn(((const float*)p)[i]);
        default:     return ((const uint32_t*)p)[i];
    }
}

// ---------------- prep: Shoup twiddle-pair tables ----------------
__device__ __forceinline__ uint2 shoup_pair(uint32_t w) {
    uint32_t wp = (uint32_t)((((unsigned long long)w) << 32) / MOD);
    return make_uint2(w, wp);
}
__global__ void __launch_bounds__(1024) ntt_prep(const void* __restrict__ tw,
                                                 const void* __restrict__ ninv) {
    int gid = blockIdx.x * 1024 + threadIdx.x;          // 3 blocks: 0..3071
    int dt = probe_dtype(tw);
    if (gid < 1024) {
        uint32_t w = load_elem(tw, (size_t)gid << 11, dt);        // plain
        g_T1[gid]        = shoup_pair(w);
        g_T1[gid + 1024] = shoup_pair(MOD - w);         // omega^-{2^21} = -1
    } else {
        int j = gid - 1024;                             // 0..2047
        unsigned long long ni = load_elem(ninv, 0, dt);
        uint32_t w = (uint32_t)((unsigned long long)load_elem(tw, j, dt)
                                * ni % MOD);            // omega^-j * n_inv
        g_T2[j] = shoup_pair(w);
    }
    if (gid == 0) g_dtype = dt;
}

// ---------------- pass A: 2 columns per CTA (2 CTAs/SM) ----------------
__global__ void __launch_bounds__(512, 2) ntt_pass_a(const void* __restrict__ in) {
    extern __shared__ uint4 smem_raw[];
    uint4* sdata = smem_raw;                            // 2 x COLPAD
    uint2* sT1   = (uint2*)(smem_raw + 2 * COLPAD);     // 2048
    uint2* sT2   = sT1 + 2048;                          // 2048
    int t  = threadIdx.x;
    int c0 = blockIdx.x * 2;
    int dt = g_dtype;
    for (int i = t; i < 2048; i += 512) { sT1[i] = g_T1[i]; sT2[i] = g_T2[i]; }

    // Load phase: lanes {0,1} cover the 2 columns of one row (64B contiguous
    // for int64). 8 iterations x 256 rows.
    {
        int c = t & 1;
        int tp = t >> 1;
        if (dt == DT_I64) {
#pragma unroll
            for (int it = 0; it < 8; ++it) {
                int p = it * 256 + tp;
                size_t idx = ((size_t)p * 2048 + c0 + c) * 2;  // ulonglong2 units
                ulonglong2 a = __ldcs((const ulonglong2*)in + idx);
                ulonglong2 b = __ldcs((const ulonglong2*)in + idx + 1);
                sdata[c * COLPAD + padi(p)] =
                    make_uint4((uint32_t)a.x, (uint32_t)a.y,
                               (uint32_t)b.x, (uint32_t)b.y);
            }
        } else if (dt == DT_I32) {
#pragma unroll
            for (int it = 0; it < 8; ++it) {
                int p = it * 256 + tp;
                sdata[c * COLPAD + padi(p)] =
                    __ldcs((const uint4*)in + (size_t)p * 2048 + c0 + c);
            }
        } else if (dt == DT_F64) {
#pragma unroll
            for (int it = 0; it < 8; ++it) {
                int p = it * 256 + tp;
                size_t idx = ((size_t)p * 2048 + c0 + c) * 2;
                double2 a = __ldcs((const double2*)in + idx);
                double2 b = __ldcs((const double2*)in + idx + 1);
                sdata[c * COLPAD + padi(p)] =
                    make_uint4((uint32_t)__double2ll_rn(a.x),
                               (uint32_t)__double2ll_rn(a.y),
                               (uint32_t)__double2ll_rn(b.x),
                               (uint32_t)__double2ll_rn(b.y));
            }
        } else {
#pragma unroll
            for (int it = 0; it < 8; ++it) {
                int p = it * 256 + tp;
                float4 f = __ldcs((const float4*)in + (size_t)p * 2048 + c0 + c);
                sdata[c * COLPAD + padi(p)] =
                    make_uint4((uint32_t)__float2ll_rn(f.x),
                               (uint32_t)__float2ll_rn(f.y),
                               (uint32_t)__float2ll_rn(f.z),
                               (uint32_t)__float2ll_rn(f.w));
            }
        }
    }
    __syncthreads();                                    // cross-group staging

    // Transform phase: group g = t>>8 owns column c0+g; named barriers only.
    int g    = t >> 8;
    int tloc = t & 255;
    uint4* smcol = sdata + g * COLPAD;
    uint4 x[8];
#pragma unroll
    for (int j = 0; j < 8; ++j) x[j] = smcol[padi(tloc + 256 * j)];
    dif2048(x, tloc, smcol, sT1, 1 + g);
#pragma unroll
    for (int j = 0; j < 8; ++j) {                       // fused scale, back to smem
        int r = 8 * tloc + j;
        unsigned k2 = __brev((unsigned)r) >> 21;
        unsigned e  = (unsigned)(c0 + g) * k2;          // < 2^22
        uint2 w1 = sT1[e >> 11];
        uint2 w2 = sT2[e & 2047];
        uint4 v = x[j];                                 // v *= w1*w2 (two shoups)
        v.x = shmul(w2, shmul(w1, v.x));
        v.y = shmul(w2, shmul(w1, v.y));
        v.z = shmul(w2, shmul(w1, v.z));
        v.w = shmul(w2, shmul(w1, v.w));
        smcol[padi(r)] = v;
    }
    __syncthreads();                                    // cross-group staging

    // Store phase: 32B-contiguous chunks (2 cols x 16B per row r).
    {
        int c = t & 1;
        int tp = t >> 1;
#pragma unroll
        for (int it = 0; it < 8; ++it) {
            int r = it * 256 + tp;
            g_buf[((size_t)r << 11) + c0 + c] = sdata[c * COLPAD + padi(r)];
        }
    }
}

// ---------------- pass B: 2 rows per CTA (2 CTAs/SM), f32 output ----------------
__global__ void __launch_bounds__(512, 2) ntt_pass_b(float* __restrict__ out) {
    extern __shared__ uint4 smem_raw[];
    uint4* sdata = smem_raw;                            // 2 x COLPAD
    uint2* sT1   = (uint2*)(smem_raw + 2 * COLPAD);     // 1024 (butterfly half)
    int t = threadIdx.x;
    int B = blockIdx.x;                                 // 0..1023
    for (int i = t; i < 1024; i += 512) sT1[i] = g_T1[i];

    // Group g transforms row B + 1024g; its k2 = 2*brev10(B) + g.
    int g    = t >> 8;
    int tloc = t & 255;
    int row  = B + (g << 10);
    uint4* smcol = sdata + g * COLPAD;
    const uint4* src = g_buf + ((size_t)row << 11);
    uint4 x[8];
#pragma unroll
    for (int j = 0; j < 8; ++j) x[j] = src[tloc + 256 * j];   // coalesced
    __syncthreads();                                    // sT1 ready
    dif2048(x, tloc, smcol, sT1, 1 + g);
#pragma unroll
    for (int j = 0; j < 8; ++j) {                       // f32 bit patterns to smem
        int r = 8 * tloc + j;
        smcol[padi(r)] = make_uint4(__float_as_uint((float)x[j].x),
                                    __float_as_uint((float)x[j].y),
                                    __float_as_uint((float)x[j].z),
                                    __float_as_uint((float)x[j].w));
    }
    __syncthreads();                                    // cross-group staging

    // Store: out point (2K + c) + 2048*k1; c in {0,1} -> 32B sector chunks.
    {
        unsigned K = __brev((unsigned)B) >> 22;         // brev10(B)
        int c  = t & 1;                                 // group bit (brev1 = id)
        int tp = t >> 1;
#pragma unroll
        for (int it = 0; it < 8; ++it) {
            int jj = it * 256 + tp;
            unsigned k1 = __brev((unsigned)jj) >> 21;
            size_t o = (size_t)(2 * K + c) + ((size_t)k1 << 11);
            __stcs((uint4*)out + o, sdata[c * COLPAD + padi(jj)]);
        }
    }
}

extern "C" void kernel_launch(void* const* d_in, const int* in_sizes, int n_in,
                              void* d_out, int out_size) {
    // Identify inputs by element count: input = 2^24, twiddles = 2^21, n_inv = 1.
    const void* in = nullptr; const void* tw = nullptr; const void* ninv = nullptr;
    for (int i = 0; i < n_in; ++i) {
        if (in_sizes[i] == (int)(N_FULL * 4)) in = d_in[i];
        else if (in_sizes[i] == (int)N_HALF) tw = d_in[i];
        else ninv = d_in[i];
    }
    static bool attr_set = false;
    if (!attr_set) {
        cudaFuncSetAttribute(ntt_pass_a,
            cudaFuncAttributeMaxDynamicSharedMemorySize, SMEM_A_BYTES);
        cudaFuncSetAttribute(ntt_pass_b,
            cudaFuncAttributeMaxDynamicSharedMemorySize, SMEM_B_BYTES);
        attr_set = true;
    }
    ntt_prep  <<<   3, 1024>>>(tw, ninv);
    ntt_pass_a<<<1024,  512, SMEM_A_BYTES>>>(in);
    ntt_pass_b<<<1024,  512, SMEM_B_BYTES>>>((float*)d_out);
}

// round 14
// speedup vs baseline: 1.1861x; 1.1861x over previous
#include <cuda_runtime.h>
#include <cstdint>

// ============================================================================
// Inverse NTT over F_P, P = 2013265921, N = 2^22, C = 4. Four-step 2048x2048.
// R14 = R13 with the OFFH constexpr->macro compile fix.
// R13 = R11 (Montgomery, 2-col/2-row 512-thread CTAs, 2 CTAs/SM, named
// barriers, lazy subtract) + STAGE-INDEXED twiddle tables:
//   Tst[OFFH(H)+i] = T1[i*1024/H], OFFH(H) = 2048-2H
// so every butterfly's twiddle LDS is unit-stride across lanes ->
// bank-conflict-free (R11 had 8/16-way conflicts on middle stages).
// ============================================================================

static constexpr uint32_t MOD    = 2013265921u;
static constexpr uint32_t N_FULL = 1u << 22;
static constexpr uint32_t N_HALF = 1u << 21;

static constexpr uint32_t calc_pinv() {
    uint32_t x = MOD;
    for (int i = 0; i < 5; ++i) x *= 2u - MOD * x;
    return x;
}
static constexpr uint32_t PINV_NEG = (uint32_t)(0u - calc_pinv());

static constexpr uint32_t calc_r2() {     // 2^64 mod P
    unsigned long long r = 1;
    for (int i = 0; i < 64; ++i) { r <<= 1; if (r >= MOD) r -= MOD; }
    return (uint32_t)r;
}
static constexpr uint32_t R2 = calc_r2();

#define DT_I32 0
#define DT_I64 1
#define DT_F32 2
#define DT_F64 3

static constexpr int COLPAD = 2305;       // padded uint4 stride per column
static constexpr int SMEM_A_BYTES = 2 * COLPAD * 16 + 3 * 2048 * 4;  // 98336
static constexpr int SMEM_B_BYTES = 2 * COLPAD * 16 + 2048 * 4;      // 81952

#define OFFH(H) (2048 - 2 * (H))          // stage-table base (macro: device-safe)

__device__ uint32_t g_T1[2048];           // Montgomery omega^-{2048k} (full)
__device__ uint32_t g_T2[2048];           // Montgomery omega^-j * n_inv
__device__ uint32_t g_Tst[2048];          // stage-indexed butterfly twiddles
__device__ uint4    g_buf[N_FULL];        // 64 MB intermediate
__device__ int      g_dtype;

// Named barrier: 256 threads of group (id-1). Per-CTA resource.
#define NB(id) asm volatile("bar.sync %0, 256;" :: "r"(id) : "memory")

// ---------------- modular primitives (branch-free) ----------------
__device__ __forceinline__ uint32_t mmul(uint32_t a, uint32_t b) {
    // a < P (twiddle), b < 2P allowed: r < 1.938P, single min -> [0,P).
    unsigned long long t = (unsigned long long)a * b;
    uint32_t m = (uint32_t)t * PINV_NEG;
    uint32_t r = (uint32_t)((t + (unsigned long long)m * MOD) >> 32);
    return min(r, r - MOD);
}
__device__ __forceinline__ uint32_t addm(uint32_t a, uint32_t b) {
    uint32_t s = a + b; return min(s, s - MOD);
}
__device__ __forceinline__ uint32_t subm(uint32_t a, uint32_t b) {
    uint32_t d = a - b; return min(d, d + MOD);
}
__device__ __forceinline__ uint32_t subl(uint32_t a, uint32_t b) {
    return a - b + MOD;                   // lazy: < 2P, only feeds mmul
}

__device__ __forceinline__ void bfly(uint4& lo, uint4& hi, uint32_t tw) {
    uint32_t a, d;
    a = addm(lo.x, hi.x); d = subl(lo.x, hi.x); lo.x = a; hi.x = mmul(tw, d);
    a = addm(lo.y, hi.y); d = subl(lo.y, hi.y); lo.y = a; hi.y = mmul(tw, d);
    a = addm(lo.z, hi.z); d = subl(lo.z, hi.z); lo.z = a; hi.z = mmul(tw, d);
    a = addm(lo.w, hi.w); d = subl(lo.w, hi.w); lo.w = a; hi.w = mmul(tw, d);
}
__device__ __forceinline__ void bfly1(uint4& lo, uint4& hi) {   // twiddle == 1
    uint32_t a, d;
    a = addm(lo.x, hi.x); d = subm(lo.x, hi.x); lo.x = a; hi.x = d;
    a = addm(lo.y, hi.y); d = subm(lo.y, hi.y); lo.y = a; hi.y = d;
    a = addm(lo.z, hi.z); d = subm(lo.z, hi.z); lo.z = a; hi.z = d;
    a = addm(lo.w, hi.w); d = subm(lo.w, hi.w); lo.w = a; hi.w = d;
}
__device__ __forceinline__ void scale4(uint4& v, uint32_t tw) {
    v.x = mmul(tw, v.x); v.y = mmul(tw, v.y);
    v.z = mmul(tw, v.z); v.w = mmul(tw, v.w);
}

// Three consecutive DIF stages (halves 4S, 2S, S) using the stage-indexed
// table: twiddle for half H at lo-position p is Tst[OFFH(H) + (p mod H)]
// (same value as T1[(p mod H)*1024/H], but unit-stride across lanes).
template <int S>
__device__ __forceinline__ void dif_group(uint4 x[8], int base,
                                          const uint32_t* ts) {
#pragma unroll
    for (int j = 0; j < 4; ++j) {                       // half = 4S
        int p = base + j * S;
        bfly(x[j], x[j + 4], ts[OFFH(4 * S) + (p & (4 * S - 1))]);
    }
#pragma unroll
    for (int k = 0; k < 4; ++k) {                       // half = 2S
        int j = (k & 1) + ((k & 2) << 1);
        int p = base + j * S;
        bfly(x[j], x[j + 2], ts[OFFH(2 * S) + (p & (2 * S - 1))]);
    }
#pragma unroll
    for (int j = 0; j < 8; j += 2) {                    // half = S
        int p = base + j * S;
        bfly(x[j], x[j + 1], ts[OFFH(S) + (p & (S - 1))]);
    }
}

__device__ __forceinline__ int padi(int i) { return i + (i >> 3); }

// In-place size-2048 DIF (validated choreography). Entry: x[j] = point
// (t+256j). Exit: x[j] = storage slot (8t+j); slot r holds output brev11(r).
__device__ __forceinline__ void dif2048(uint4 x[8], int t, uint4* sm,
                                        const uint32_t* ts, int bid) {
    dif_group<256>(x, t, ts);                           // halves 1024,512,256
#pragma unroll
    for (int j = 0; j < 8; ++j) sm[padi(t + 256 * j)] = x[j];
    NB(bid);
    int b1 = ((t >> 5) << 8) | (t & 31);
#pragma unroll
    for (int j = 0; j < 8; ++j) x[j] = sm[padi(b1 + 32 * j)];
    dif_group<32>(x, b1, ts);                           // halves 128,64,32
    NB(bid);
#pragma unroll
    for (int j = 0; j < 8; ++j) sm[padi(b1 + 32 * j)] = x[j];
    NB(bid);
    int b2 = ((t >> 2) << 5) | (t & 3);
#pragma unroll
    for (int j = 0; j < 8; ++j) x[j] = sm[padi(b2 + 4 * j)];
    dif_group<4>(x, b2, ts);                            // halves 16,8,4
    NB(bid);
#pragma unroll
    for (int j = 0; j < 8; ++j) sm[padi(b2 + 4 * j)] = x[j];
    NB(bid);
#pragma unroll
    for (int j = 0; j < 8; ++j) x[j] = sm[padi(8 * t + j)];
    uint32_t w512 = ts[OFFH(2) + 1];                    // = T1[512]; halves 2,1
    bfly1(x[0], x[2]); bfly(x[1], x[3], w512);
    bfly1(x[4], x[6]); bfly(x[5], x[7], w512);
    bfly1(x[0], x[1]); bfly1(x[2], x[3]);
    bfly1(x[4], x[5]); bfly1(x[6], x[7]);
}

// dtype probe (tw[0] == 1 in every encoding):
//   int64: w0=1,w1=0   int32: w0=1,w1!=0   f64: w0=0   f32: w0=0x3F800000
__device__ __forceinline__ int probe_dtype(const void* tw) {
    const uint32_t* w = (const uint32_t*)tw;
    if (w[0] == 1u) return (w[1] == 0u) ? DT_I64 : DT_I32;
    if (w[0] == 0u) return DT_F64;
    return DT_F32;
}
__device__ __forceinline__ uint32_t load_elem(const void* p, size_t i, int dt) {
    switch (dt) {
        case DT_I64: return (uint32_t)((const unsigned long long*)p)[i];
        case DT_F64: return (uint32_t)__double2ll_rn(((const double*)p)[i]);
        case DT_F32: return (uint32_t)__float2ll_rn(((const float*)p)[i]);
        default:     return ((const uint32_t*)p)[i];
    }
}

// ---------------- prep: twiddle tables (5 blocks x 1024) ----------------
__global__ void __launch_bounds__(1024) ntt_prep(const void* __restrict__ tw,
                                                 const void* __restrict__ ninv) {
    int dt = probe_dtype(tw);
    if (blockIdx.x == 0) {                              // full T1 (both halves)
        uint32_t v = mmul(load_elem(tw, (size_t)threadIdx.x << 11, dt), R2);
        g_T1[threadIdx.x] = v;
        g_T1[threadIdx.x + 1024] = MOD - v;             // omega^-{2^21} = -1
        if (threadIdx.x == 0) g_dtype = dt;
    } else if (blockIdx.x <= 2) {                       // T2[j] = tw[j]*ninv
        int j = (blockIdx.x - 1) * 1024 + threadIdx.x;  // 0..2047
        uint32_t nm = mmul(load_elem(ninv, 0, dt), R2);
        g_T2[j] = mmul(mmul(load_elem(tw, j, dt), R2), nm);
    } else {                                            // stage-indexed table
        int E = (blockIdx.x - 3) * 1024 + threadIdx.x;  // 0..2047
        if (E < 2046) {                                 // max used idx = 2045
            unsigned u = 2048u - (unsigned)E;           // u in (H, 2H]
            int lg = 31 - __clz(u - 1);                 // log2 H
            int i  = (2 << lg) - (int)u;                // i < H
            // value = T1[i * 1024/H] = Montgomery omega^-{2048 * i*1024/H}
            size_t expi = (size_t)i << (21 - lg);       // (i*1024/H) << 11
            g_Tst[E] = mmul(load_elem(tw, expi, dt), R2);
        }
    }
}

// ---------------- pass A: 2 columns per CTA (2 CTAs/SM) ----------------
__global__ void __launch_bounds__(512, 2) ntt_pass_a(const void* __restrict__ in) {
    extern __shared__ uint4 smem_raw[];
    uint4*    sdata = smem_raw;                         // 2 x COLPAD
    uint32_t* sTst  = (uint32_t*)(smem_raw + 2 * COLPAD);   // 2048
    uint32_t* sT1   = sTst + 2048;                      // 2048 (full, scale)
    uint32_t* sT2   = sT1 + 2048;                       // 2048 (scale)
    int t  = threadIdx.x;
    int c0 = blockIdx.x * 2;
    int dt = g_dtype;
    for (int i = t; i < 2048; i += 512) {
        sTst[i] = g_Tst[i]; sT1[i] = g_T1[i]; sT2[i] = g_T2[i];
    }

    // Load phase: lanes {0,1} cover the 2 columns of one row (64B contiguous
    // for int64). 8 iterations x 256 rows.
    {
        int c = t & 1;
        int tp = t >> 1;
        if (dt == DT_I64) {
#pragma unroll
            for (int it = 0; it < 8; ++it) {
                int p = it * 256 + tp;
                size_t idx = ((size_t)p * 2048 + c0 + c) * 2;  // ulonglong2 units
                ulonglong2 a = __ldcs((const ulonglong2*)in + idx);
                ulonglong2 b = __ldcs((const ulonglong2*)in + idx + 1);
                sdata[c * COLPAD + padi(p)] =
                    make_uint4((uint32_t)a.x, (uint32_t)a.y,
                               (uint32_t)b.x, (uint32_t)b.y);
            }
        } else if (dt == DT_I32) {
#pragma unroll
            for (int it = 0; it < 8; ++it) {
                int p = it * 256 + tp;
                sdata[c * COLPAD + padi(p)] =
                    __ldcs((const uint4*)in + (size_t)p * 2048 + c0 + c);
            }
        } else if (dt == DT_F64) {
#pragma unroll
            for (int it = 0; it < 8; ++it) {
                int p = it * 256 + tp;
                size_t idx = ((size_t)p * 2048 + c0 + c) * 2;
                double2 a = __ldcs((const double2*)in + idx);
                double2 b = __ldcs((const double2*)in + idx + 1);
                sdata[c * COLPAD + padi(p)] =
                    make_uint4((uint32_t)__double2ll_rn(a.x),
                               (uint32_t)__double2ll_rn(a.y),
                               (uint32_t)__double2ll_rn(b.x),
                               (uint32_t)__double2ll_rn(b.y));
            }
        } else {
#pragma unroll
            for (int it = 0; it < 8; ++it) {
                int p = it * 256 + tp;
                float4 f = __ldcs((const float4*)in + (size_t)p * 2048 + c0 + c);
                sdata[c * COLPAD + padi(p)] =
                    make_uint4((uint32_t)__float2ll_rn(f.x),
                               (uint32_t)__float2ll_rn(f.y),
                               (uint32_t)__float2ll_rn(f.z),
                               (uint32_t)__float2ll_rn(f.w));
            }
        }
    }
    __syncthreads();                                    // cross-group staging

    // Transform phase: group g = t>>8 owns column c0+g; named barriers only.
    int g    = t >> 8;
    int tloc = t & 255;
    uint4* smcol = sdata + g * COLPAD;
    uint4 x[8];
#pragma unroll
    for (int j = 0; j < 8; ++j) x[j] = smcol[padi(tloc + 256 * j)];
    dif2048(x, tloc, smcol, sTst, 1 + g);
#pragma unroll
    for (int j = 0; j < 8; ++j) {                       // fused scale, back to smem
        int r = 8 * tloc + j;
        unsigned k2 = __brev((unsigned)r) >> 21;
        unsigned e  = (unsigned)(c0 + g) * k2;          // < 2^22
        uint32_t w  = mmul(sT1[e >> 11], sT2[e & 2047]);
        scale4(x[j], w);
        smcol[padi(r)] = x[j];
    }
    __syncthreads();                                    // cross-group staging

    // Store phase: 32B-contiguous chunks (2 cols x 16B per row r).
    {
        int c = t & 1;
        int tp = t >> 1;
#pragma unroll
        for (int it = 0; it < 8; ++it) {
            int r = it * 256 + tp;
            g_buf[((size_t)r << 11) + c0 + c] = sdata[c * COLPAD + padi(r)];
        }
    }
}

// ---------------- pass B: 2 rows per CTA (2 CTAs/SM), f32 output ----------------
__global__ void __launch_bounds__(512, 2) ntt_pass_b(float* __restrict__ out) {
    extern __shared__ uint4 smem_raw[];
    uint4*    sdata = smem_raw;                         // 2 x COLPAD
    uint32_t* sTst  = (uint32_t*)(smem_raw + 2 * COLPAD);   // 2048
    int t = threadIdx.x;
    int B = blockIdx.x;                                 // 0..1023
    for (int i = t; i < 2048; i += 512) sTst[i] = g_Tst[i];

    // Group g transforms row B + 1024g; its k2 = 2*brev10(B) + g.
    int g    = t >> 8;
    int tloc = t & 255;
    int row  = B + (g << 10);
    uint4* smcol = sdata + g * COLPAD;
    const uint4* src = g_buf + ((size_t)row << 11);
    uint4 x[8];
#pragma unroll
    for (int j = 0; j < 8; ++j) x[j] = src[tloc + 256 * j];   // coalesced
    __syncthreads();                                    // sTst ready
    dif2048(x, tloc, smcol, sTst, 1 + g);
#pragma unroll
    for (int j = 0; j < 8; ++j) {                       // f32 bit patterns to smem
        int r = 8 * tloc + j;
        smcol[padi(r)] = make_uint4(__float_as_uint((float)x[j].x),
                                    __float_as_uint((float)x[j].y),
                                    __float_as_uint((float)x[j].z),
                                    __float_as_uint((float)x[j].w));
    }
    __syncthreads();                                    // cross-group staging

    // Store: out point (2K + c) + 2048*k1; c in {0,1} -> 32B sector chunks.
    {
        unsigned K = __brev((unsigned)B) >> 22;         // brev10(B)
        int c  = t & 1;                                 // group bit (brev1 = id)
        int tp = t >> 1;
#pragma unroll
        for (int it = 0; it < 8; ++it) {
            int jj = it * 256 + tp;
            unsigned k1 = __brev((unsigned)jj) >> 21;
            size_t o = (size_t)(2 * K + c) + ((size_t)k1 << 11);
            __stcs((uint4*)out + o, sdata[c * COLPAD + padi(jj)]);
        }
    }
}

extern "C" void kernel_launch(void* const* d_in, const int* in_sizes, int n_in,
                              void* d_out, int out_size) {
    // Identify inputs by element count: input = 2^24, twiddles = 2^21, n_inv = 1.
    const void* in = nullptr; const void* tw = nullptr; const void* ninv = nullptr;
    for (int i = 0; i < n_in; ++i) {
        if (in_sizes[i] == (int)(N_FULL * 4)) in = d_in[i];
        else if (in_sizes[i] == (int)N_HALF) tw = d_in[i];
        else ninv = d_in[i];
    }
    static bool attr_set = false;
    if (!attr_set) {
        cudaFuncSetAttribute(ntt_pass_a,
            cudaFuncAttributeMaxDynamicSharedMemorySize, SMEM_A_BYTES);
        cudaFuncSetAttribute(ntt_pass_b,
            cudaFuncAttributeMaxDynamicSharedMemorySize, SMEM_B_BYTES);
        attr_set = true;
    }
    ntt_prep  <<<   5, 1024>>>(tw, ninv);
    ntt_pass_a<<<1024,  512, SMEM_A_BYTES>>>(in);
    ntt_pass_b<<<1024,  512, SMEM_B_BYTES>>>((float*)d_out);
}